// round 15
// baseline (speedup 1.0000x reference)
#include <cuda_runtime.h>
#include <cuda_bf16.h>
#include <cstdint>

#define N_PTS 8192
#define DIM 64
#define BM 128
#define NT (N_PTS / BM)            // 64 tiles per side
#define NPAIR (NT * (NT + 1) / 2)  // 2080 tile pairs
#define NTHREADS 512
#define TILE_B 16384               // 128 rows x 64 bf16 (128B rows)
#define NQ 4                       // partial quarters per tile side
#define GRID 152                   // persistent CTAs
#define BUF_B (4 * TILE_B + 4096)  // 4 tiles + 256 float4 metadata
#define NCLS 16

// ---- scratch (device globals; all writes idempotent, replay-safe) ----
__device__ __align__(16) __nv_bfloat16 g_xhi[N_PTS * DIM];
__device__ __align__(16) __nv_bfloat16 g_xlo[N_PTS * DIM];
__device__ __align__(16) float4 g_meta[N_PTS];   // (sq, ru, lab_bits, 0)
__device__ float g_pse[NQ * NT * N_PTS];
__device__ float g_psl[NQ * NT * N_PTS];
__device__ float g_blocksum[N_PTS / 256];

typedef unsigned long long u64t;

__device__ __forceinline__ uint32_t smem_u32(const void* p) {
    uint32_t a;
    asm("{ .reg .u64 t; cvta.to.shared.u64 t, %1; cvt.u32.u64 %0, t; }" : "=r"(a) : "l"(p));
    return a;
}
__device__ __forceinline__ float fast_sqrt(float x) {
    float r; asm("sqrt.approx.f32 %0, %1;" : "=f"(r) : "f"(x)); return r;
}
__device__ __forceinline__ u64t pk2(float lo, float hi) {
    u64t r; asm("mov.b64 %0, {%1,%2};" : "=l"(r) : "f"(lo), "f"(hi)); return r;
}
__device__ __forceinline__ void upk2(float& lo, float& hi, u64t v) {
    asm("mov.b64 {%0,%1}, %2;" : "=f"(lo), "=f"(hi) : "l"(v));
}
__device__ __forceinline__ u64t fma2_(u64t a, u64t b, u64t c) {
    u64t r; asm("fma.rn.f32x2 %0,%1,%2,%3;" : "=l"(r) : "l"(a), "l"(b), "l"(c)); return r;
}
__device__ __forceinline__ u64t add2_(u64t a, u64t b) {
    u64t r; asm("add.rn.f32x2 %0,%1,%2;" : "=l"(r) : "l"(a), "l"(b)); return r;
}
__device__ __forceinline__ u64t mul2_(u64t a, u64t b) {
    u64t r; asm("mul.rn.f32x2 %0,%1,%2;" : "=l"(r) : "l"(a), "l"(b)); return r;
}
__device__ __forceinline__ void ldsm4(uint32_t* r, uint32_t addr) {
    asm volatile("ldmatrix.sync.aligned.m8n8.x4.shared.b16 {%0,%1,%2,%3}, [%4];"
                 : "=r"(r[0]), "=r"(r[1]), "=r"(r[2]), "=r"(r[3]) : "r"(addr));
}
__device__ __forceinline__ void mma_bf16(float* d, const uint32_t* a,
                                         uint32_t b0, uint32_t b1) {
    asm("mma.sync.aligned.m16n8k16.row.col.f32.bf16.bf16.f32 "
        "{%0,%1,%2,%3}, {%4,%5,%6,%7}, {%8,%9}, {%0,%1,%2,%3};"
        : "+f"(d[0]), "+f"(d[1]), "+f"(d[2]), "+f"(d[3])
        : "r"(a[0]), "r"(a[1]), "r"(a[2]), "r"(a[3]), "r"(b0), "r"(b1));
}
__device__ __forceinline__ void cp16(uint32_t dst, const void* src) {
    asm volatile("cp.async.cg.shared.global [%0], [%1], 16;" :: "r"(dst), "l"(src));
}
#define CP_COMMIT() asm volatile("cp.async.commit_group;" ::: "memory")
#define CP_WAIT1()  asm volatile("cp.async.wait_group 1;" ::: "memory")

__device__ __forceinline__ void decode_pair(int b, int& ti, int& tj) {
    int t = (int)floorf((129.0f - sqrtf(16641.0f - 8.0f * (float)b)) * 0.5f);
    if (t < 0) t = 0;
    if (t > NT - 1) t = NT - 1;
    while (t > 0 && b < t * (129 - t) / 2) t--;
    while (b >= (t + 1) * (128 - t) / 2) t++;
    ti = t;
    tj = t + (b - t * (129 - t) / 2);
}

// ---- prep ----
__global__ void prep_kernel(const float* __restrict__ pts,
                            const long long* __restrict__ labs) {
    int i = blockIdx.x * blockDim.x + threadIdx.x;
    if (i >= N_PTS) return;
    float s = 0.f;
#pragma unroll
    for (int q = 0; q < DIM; q++) {
        float x = pts[i * DIM + q];
        s = fmaf(x, x, s);
        __nv_bfloat16 hi = __float2bfloat16(x);
        __nv_bfloat16 lo = __float2bfloat16(x - __bfloat162float(hi));
        g_xhi[i * DIM + q] = hi;
        g_xlo[i * DIM + q] = lo;
    }
    float4 m;
    m.x = s;
    m.y = 1.0f / (1.0f - s);
    m.z = __int_as_float(((int)labs[i]) & (NCLS - 1));
    m.w = 0.f;
    g_meta[i] = m;
}

// ---- async prefetch of one pair's tiles + metadata into a smem buffer ----
__device__ __forceinline__ void prefetch_pair(uint32_t dbuf, int i0, int j0, int tid) {
    const uint4* HI = (const uint4*)g_xhi;
    const uint4* LO = (const uint4*)g_xlo;
#pragma unroll
    for (int it = 0; it < 8; it++) {
        int idx = tid + it * NTHREADS;              // 0..4095
        int tile = idx >> 10;                       // 0:Ah 1:Al 2:Bh 3:Bl
        int cidx = idx & 1023;
        int row = cidx >> 3, q = cidx & 7;
        int base = (tile & 2) ? j0 : i0;
        const uint4* src = (tile & 1) ? LO : HI;
        uint32_t off = (uint32_t)(row * 128) + (uint32_t)((q ^ (row & 7)) << 4);
        cp16(dbuf + tile * TILE_B + off, &src[(base + row) * 8 + q]);
    }
    if (tid < 256) {                                // 0..127: i rows, 128..255: j cols
        int g = ((tid >> 7) ? j0 : i0) + (tid & 127);
        cp16(dbuf + 4 * TILE_B + tid * 16, &g_meta[g]);
    }
}

// ---- shared GEMM body: 3-term split HMMA, term-major ----
__device__ __forceinline__ void gemm_pair(uint32_t dbuf, float d[2][4][4],
                                          int mr, int nc, int t8, int rs) {
#pragma unroll
    for (int mf = 0; mf < 2; mf++)
#pragma unroll
        for (int nb = 0; nb < 4; nb++)
#pragma unroll
            for (int k = 0; k < 4; k++) d[mf][nb][k] = 0.f;

#pragma unroll
    for (int ks = 0; ks < 4; ks++) {
        uint32_t ah[2][4], al[2][4], bh[2][4], bl[2][4];
#pragma unroll
        for (int mf = 0; mf < 2; mf++) {
            int rowA = mr + mf * 16 + (t8 & 1) * 8 + rs;
            int ch = ks * 2 + (t8 >> 1);
            uint32_t sw = (uint32_t)(rowA * 128) + (uint32_t)((ch ^ (rowA & 7)) << 4);
            ldsm4(ah[mf], dbuf + 0 * TILE_B + sw);
            ldsm4(al[mf], dbuf + 1 * TILE_B + sw);
        }
#pragma unroll
        for (int nbp = 0; nbp < 2; nbp++) {
            int rowB = nc + nbp * 16 + (t8 >> 1) * 8 + rs;
            int ch = ks * 2 + (t8 & 1);
            uint32_t sw = (uint32_t)(rowB * 128) + (uint32_t)((ch ^ (rowB & 7)) << 4);
            ldsm4(bh[nbp], dbuf + 2 * TILE_B + sw);
            ldsm4(bl[nbp], dbuf + 3 * TILE_B + sw);
        }
#pragma unroll
        for (int mf = 0; mf < 2; mf++)
#pragma unroll
            for (int nbp = 0; nbp < 2; nbp++)
#pragma unroll
                for (int nbi = 0; nbi < 2; nbi++)
                    mma_bf16(d[mf][nbp * 2 + nbi], ah[mf],
                             bh[nbp][2 * nbi], bh[nbp][2 * nbi + 1]);
#pragma unroll
        for (int mf = 0; mf < 2; mf++)
#pragma unroll
            for (int nbp = 0; nbp < 2; nbp++)
#pragma unroll
                for (int nbi = 0; nbi < 2; nbi++)
                    mma_bf16(d[mf][nbp * 2 + nbi], ah[mf],
                             bl[nbp][2 * nbi], bl[nbp][2 * nbi + 1]);
#pragma unroll
        for (int mf = 0; mf < 2; mf++)
#pragma unroll
            for (int nbp = 0; nbp < 2; nbp++)
#pragma unroll
                for (int nbi = 0; nbi < 2; nbi++)
                    mma_bf16(d[mf][nbp * 2 + nbi], al[mf],
                             bh[nbp][2 * nbi], bh[nbp][2 * nbi + 1]);
    }
}

// ---- off-diagonal pair: packed f32x2 epilogue ----
__device__ __forceinline__ void compute_offdiag(uint32_t dbuf, const char* dbufp,
                                                int ti, int tj, int i0, int j0,
                                                int lane, int wr, int wc) {
    int mr = wr * 32, nc = wc * 32;
    float d[2][4][4];
    gemm_pair(dbuf, d, mr, nc, lane >> 3, lane & 7);

    const float4* meta_i = (const float4*)(dbufp + 4 * TILE_B);
    const float4* meta_j = meta_i + 128;

    u64t sqr2[4], rur2[4];
    int labr[4], rloc4[4];
#pragma unroll
    for (int f = 0; f < 4; f++) {
        int rloc = mr + (f >> 1) * 16 + (f & 1) * 8 + (lane >> 2);
        rloc4[f] = rloc;
        float4 m = meta_i[rloc];
        sqr2[f] = pk2(m.x, m.x);
        rur2[f] = pk2(2.0f * m.y, 2.0f * m.y);
        labr[f] = __float_as_int(m.z);
    }
    const u64t ONE2 = pk2(1.f, 1.f);
    const u64t N22 = pk2(-2.f, -2.f);
    const u64t NEG12 = pk2(-1.f, -1.f);
    u64t rse2[4], rpr2[4];
#pragma unroll
    for (int f = 0; f < 4; f++) { rse2[f] = pk2(0.f, 0.f); rpr2[f] = ONE2; }

#pragma unroll
    for (int nb = 0; nb < 4; nb++) {
        int cl0 = nc + nb * 8 + (lane & 3) * 2;
        float4 mj0 = meta_j[cl0], mj1 = meta_j[cl0 + 1];
        u64t mjx = pk2(mj0.x, mj1.x);
        u64t mjy = pk2(mj0.y, mj1.y);
        int lj0 = __float_as_int(mj0.z), lj1 = __float_as_int(mj1.z);
        u64t cse2 = pk2(0.f, 0.f), cpr2 = ONE2;
#pragma unroll
        for (int f = 0; f < 4; f++) {
            u64t dot = pk2(d[f >> 1][nb][(f & 1) * 2 + 0],
                           d[f >> 1][nb][(f & 1) * 2 + 1]);
            u64t sqd = fma2_(N22, dot, add2_(sqr2[f], mjx));
            u64t zz = fma2_(mul2_(sqd, rur2[f]), mjy, ONE2);
            u64t tt = fma2_(zz, zz, NEG12);
            float z0, z1, t0, t1;
            upk2(z0, z1, zz);
            upk2(t0, t1, tt);
            // rv = exp(-d) = z - sqrt(z^2-1); clamp absorbs any NaN/negative
            float rv0 = fmaxf(z0 - fast_sqrt(t0), 1e-6f);
            float rv1 = fmaxf(z1 - fast_sqrt(t1), 1e-6f);
            u64t rv2 = pk2(rv0, rv1);
            u64t rvp2 = pk2((labr[f] == lj0) ? rv0 : 1.f,
                            (labr[f] == lj1) ? rv1 : 1.f);
            rse2[f] = add2_(rse2[f], rv2);
            rpr2[f] = mul2_(rpr2[f], rvp2);
            cse2 = add2_(cse2, rv2);
            cpr2 = mul2_(cpr2, rvp2);
        }
        // col-side reduce over lane>>2; each half is one column
        float cse0, cse1, cpr0, cpr1;
        upk2(cse0, cse1, cse2);
        upk2(cpr0, cpr1, cpr2);
        float csl0 = __log2f(cpr0), csl1 = __log2f(cpr1);
#pragma unroll
        for (int s = 4; s <= 16; s <<= 1) {
            cse0 += __shfl_xor_sync(0xffffffffu, cse0, s);
            csl0 += __shfl_xor_sync(0xffffffffu, csl0, s);
            cse1 += __shfl_xor_sync(0xffffffffu, cse1, s);
            csl1 += __shfl_xor_sync(0xffffffffu, csl1, s);
        }
        if (lane < 4) {
            int cstore = nc + nb * 8 + lane * 2;
            int slot = (ti * NQ + wr) * N_PTS + (j0 + cstore);
            *(float2*)&g_pse[slot] = make_float2(cse0, cse1);
            *(float2*)&g_psl[slot] =
                make_float2(csl0 * 0.69314718055994531f,
                            csl1 * 0.69314718055994531f);
        }
    }

    // row-side: fold packed halves, reduce over lane&3
#pragma unroll
    for (int f = 0; f < 4; f++) {
        float a, b, pa, pb;
        upk2(a, b, rse2[f]);
        upk2(pa, pb, rpr2[f]);
        float se = a + b;
        float sl = __log2f(pa * pb);   // 8 factors >= ~6e-21 > FLT_MIN
        se += __shfl_xor_sync(0xffffffffu, se, 1);
        sl += __shfl_xor_sync(0xffffffffu, sl, 1);
        se += __shfl_xor_sync(0xffffffffu, se, 2);
        sl += __shfl_xor_sync(0xffffffffu, sl, 2);
        if ((lane & 3) == 0) {
            int slot = (tj * NQ + wc) * N_PTS + (i0 + rloc4[f]);
            g_pse[slot] = se;
            g_psl[slot] = sl * 0.69314718055994531f;
        }
    }
}

// ---- diagonal pair: verified scalar epilogue (64/2080 pairs) ----
__device__ __forceinline__ void compute_diag(uint32_t dbuf, const char* dbufp,
                                             int ti, int tj, int i0, int j0,
                                             int lane, int wr, int wc) {
    int mr = wr * 32, nc = wc * 32;
    float d[2][4][4];
    gemm_pair(dbuf, d, mr, nc, lane >> 3, lane & 7);

    const float4* meta_i = (const float4*)(dbufp + 4 * TILE_B);
    const float4* meta_j = meta_i + 128;

    float sqr[4], rur[4];
    int labr[4], rloc4[4];
#pragma unroll
    for (int f = 0; f < 4; f++) {
        int rloc = mr + (f >> 1) * 16 + (f & 1) * 8 + (lane >> 2);
        rloc4[f] = rloc;
        float4 m = meta_i[rloc];
        sqr[f] = m.x; rur[f] = 2.0f * m.y; labr[f] = __float_as_int(m.z);
    }
    float rse[4], rpr[4];
#pragma unroll
    for (int f = 0; f < 4; f++) { rse[f] = 0.f; rpr[f] = 1.f; }

#pragma unroll
    for (int nb = 0; nb < 4; nb++) {
#pragma unroll
        for (int ki = 0; ki < 2; ki++) {
            int cloc = nc + nb * 8 + (lane & 3) * 2 + ki;
            float4 mj = meta_j[cloc];
            int lj = __float_as_int(mj.z);
#pragma unroll
            for (int f = 0; f < 4; f++) {
                float dot = d[f >> 1][nb][(f & 1) * 2 + ki];
                float sqd = fmaxf(fmaf(-2.0f, dot, sqr[f] + mj.x), 0.f);
                float z = fmaf(sqd * rur[f], mj.y, 1.0f);
                float s = fast_sqrt(fmaf(z, z, -1.0f));
                float rv = fmaxf(z - s, 1e-6f);
                bool offd = (rloc4[f] != cloc);
                bool pos = offd && (labr[f] == lj);
                rse[f] += offd ? rv : 0.f;
                rpr[f] *= pos ? rv : 1.f;
            }
        }
    }
#pragma unroll
    for (int f = 0; f < 4; f++) {
        float se = rse[f];
        float sl = __log2f(rpr[f]);
        se += __shfl_xor_sync(0xffffffffu, se, 1);
        sl += __shfl_xor_sync(0xffffffffu, sl, 1);
        se += __shfl_xor_sync(0xffffffffu, se, 2);
        sl += __shfl_xor_sync(0xffffffffu, sl, 2);
        if ((lane & 3) == 0) {
            int slot = (tj * NQ + wc) * N_PTS + (i0 + rloc4[f]);
            g_pse[slot] = se;
            g_psl[slot] = sl * 0.69314718055994531f;
        }
    }
}

// ---- main: persistent double-buffered HMMA pipeline ----
__global__ __launch_bounds__(NTHREADS, 1)
void main_kernel() {
    extern __shared__ __align__(16) char dsm_raw[];
    uint32_t dsm0 = smem_u32(dsm_raw);
    uint32_t dsm = (dsm0 + 127u) & ~127u;
    char* dsmp = dsm_raw + (dsm - dsm0);

    int tid = threadIdx.x;
    int w = tid >> 5, lane = tid & 31;
    int wr = w & 3, wc = w >> 2;

    int p = blockIdx.x;
    int ti = 0, tj = 0;
    if (p < NPAIR) {
        decode_pair(p, ti, tj);
        prefetch_pair(dsm, ti * BM, tj * BM, tid);
    }
    CP_COMMIT();

    int it = 0;
    for (; p < NPAIR; p += GRID, it++) {
        uint32_t dbuf = dsm + (uint32_t)(it & 1) * BUF_B;
        const char* dbufp = dsmp + (it & 1) * BUF_B;

        int tin = 0, tjn = 0;
        int pn = p + GRID;
        if (pn < NPAIR) {
            decode_pair(pn, tin, tjn);
            prefetch_pair(dsm + (uint32_t)((it + 1) & 1) * BUF_B,
                          tin * BM, tjn * BM, tid);
        }
        CP_COMMIT();
        CP_WAIT1();
        __syncthreads();

        if (ti == tj)
            compute_diag(dbuf, dbufp, ti, tj, ti * BM, tj * BM, lane, wr, wc);
        else
            compute_offdiag(dbuf, dbufp, ti, tj, ti * BM, tj * BM, lane, wr, wc);
        __syncthreads();

        ti = tin; tj = tjn;
    }
}

// ---- rowred: label histogram + per-row loss + per-block partial sum ----
__global__ void rowred_kernel() {
    __shared__ int hist[NCLS];
    __shared__ float red[256];
    int t = threadIdx.x;
    if (t < NCLS) hist[t] = 0;
    __syncthreads();
    for (int k = t; k < N_PTS; k += 256)
        atomicAdd(&hist[__float_as_int(g_meta[k].z) & (NCLS - 1)], 1);
    __syncthreads();

    int i = blockIdx.x * blockDim.x + t;
    float se = 0.f, sl = 0.f;
#pragma unroll 8
    for (int q = 0; q < NQ * NT; q++) {
        se += g_pse[q * N_PTS + i];
        sl += g_psl[q * N_PTS + i];
    }
    int lab = __float_as_int(g_meta[i].z) & (NCLS - 1);
    int P = hist[lab] - 1;
    float logA = __logf(fmaxf(se, 1e-30f));
    red[t] = logA - sl / (float)(P > 0 ? P : 1);
    __syncthreads();
    for (int s = 128; s > 0; s >>= 1) {
        if (t < s) red[t] += red[t + s];
        __syncthreads();
    }
    if (t == 0) g_blocksum[blockIdx.x] = red[0];
}

__global__ void final_kernel(float* __restrict__ out) {
    int t = threadIdx.x;
    float v = g_blocksum[t];
#pragma unroll
    for (int s = 16; s > 0; s >>= 1)
        v += __shfl_xor_sync(0xffffffffu, v, s);
    if (t == 0) out[0] = v;
}

extern "C" void kernel_launch(void* const* d_in, const int* in_sizes, int n_in,
                              void* d_out, int out_size) {
    const float* pts = (const float*)d_in[0];
    const long long* labs = (const long long*)d_in[1];
    cudaFuncSetAttribute(main_kernel, cudaFuncAttributeMaxDynamicSharedMemorySize,
                         2 * BUF_B + 128);
    prep_kernel<<<N_PTS / 256, 256>>>(pts, labs);
    main_kernel<<<GRID, NTHREADS, 2 * BUF_B + 128>>>();
    rowred_kernel<<<N_PTS / 256, 256>>>();
    final_kernel<<<1, 32>>>((float*)d_out);
}

// round 16
// speedup vs baseline: 1.4744x; 1.4744x over previous
#include <cuda_runtime.h>
#include <cuda_bf16.h>
#include <cstdint>

#define N_PTS 8192
#define DIM 64
#define BM 128
#define NT (N_PTS / BM)            // 64 tiles per side
#define NPAIR (NT * (NT + 1) / 2)  // 2080 tile pairs
#define NTHREADS 512
#define TILE_B 16384               // 128 rows x 64 bf16 (128B rows)
#define NQ 4                       // partial quarters per tile side
#define GRID 152                   // persistent CTAs
#define BUF_B (4 * TILE_B + 4096)  // 4 tiles + 256 float4 metadata
#define NCLS 16

// ---- scratch (device globals; all writes idempotent, replay-safe) ----
__device__ __align__(16) __nv_bfloat16 g_xhi[N_PTS * DIM];
__device__ __align__(16) __nv_bfloat16 g_xlo[N_PTS * DIM];
__device__ __align__(16) float4 g_meta[N_PTS];   // (sq, ru, lab_bits, 0)
__device__ float g_pse[NQ * NT * N_PTS];
__device__ float g_psl[NQ * NT * N_PTS];
__device__ float g_blocksum[N_PTS / 256];

__device__ __forceinline__ uint32_t smem_u32(const void* p) {
    uint32_t a;
    asm("{ .reg .u64 t; cvta.to.shared.u64 t, %1; cvt.u32.u64 %0, t; }" : "=r"(a) : "l"(p));
    return a;
}
__device__ __forceinline__ float fast_sqrt(float x) {
    float r; asm("sqrt.approx.f32 %0, %1;" : "=f"(r) : "f"(x)); return r;
}
__device__ __forceinline__ void ldsm4(uint32_t* r, uint32_t addr) {
    asm volatile("ldmatrix.sync.aligned.m8n8.x4.shared.b16 {%0,%1,%2,%3}, [%4];"
                 : "=r"(r[0]), "=r"(r[1]), "=r"(r[2]), "=r"(r[3]) : "r"(addr));
}
__device__ __forceinline__ void mma_bf16(float* d, const uint32_t* a,
                                         uint32_t b0, uint32_t b1) {
    asm("mma.sync.aligned.m16n8k16.row.col.f32.bf16.bf16.f32 "
        "{%0,%1,%2,%3}, {%4,%5,%6,%7}, {%8,%9}, {%0,%1,%2,%3};"
        : "+f"(d[0]), "+f"(d[1]), "+f"(d[2]), "+f"(d[3])
        : "r"(a[0]), "r"(a[1]), "r"(a[2]), "r"(a[3]), "r"(b0), "r"(b1));
}
__device__ __forceinline__ void cp16(uint32_t dst, const void* src) {
    asm volatile("cp.async.cg.shared.global [%0], [%1], 16;" :: "r"(dst), "l"(src));
}
#define CP_COMMIT() asm volatile("cp.async.commit_group;" ::: "memory")
#define CP_WAIT1()  asm volatile("cp.async.wait_group 1;" ::: "memory")

__device__ __forceinline__ void decode_pair(int b, int& ti, int& tj) {
    int t = (int)floorf((129.0f - sqrtf(16641.0f - 8.0f * (float)b)) * 0.5f);
    if (t < 0) t = 0;
    if (t > NT - 1) t = NT - 1;
    while (t > 0 && b < t * (129 - t) / 2) t--;
    while (b >= (t + 1) * (128 - t) / 2) t++;
    ti = t;
    tj = t + (b - t * (129 - t) / 2);
}

// ---- prep ----
__global__ void prep_kernel(const float* __restrict__ pts,
                            const long long* __restrict__ labs) {
    int i = blockIdx.x * blockDim.x + threadIdx.x;
    if (i >= N_PTS) return;
    float s = 0.f;
#pragma unroll
    for (int q = 0; q < DIM; q++) {
        float x = pts[i * DIM + q];
        s = fmaf(x, x, s);
        __nv_bfloat16 hi = __float2bfloat16(x);
        __nv_bfloat16 lo = __float2bfloat16(x - __bfloat162float(hi));
        g_xhi[i * DIM + q] = hi;
        g_xlo[i * DIM + q] = lo;
    }
    float4 m;
    m.x = s;
    m.y = 1.0f / (1.0f - s);
    m.z = __int_as_float(((int)labs[i]) & (NCLS - 1));
    m.w = 0.f;
    g_meta[i] = m;
}

// ---- async prefetch of one pair's tiles + metadata into a smem buffer ----
__device__ __forceinline__ void prefetch_pair(uint32_t dbuf, int i0, int j0, int tid) {
    const uint4* HI = (const uint4*)g_xhi;
    const uint4* LO = (const uint4*)g_xlo;
#pragma unroll
    for (int it = 0; it < 8; it++) {
        int idx = tid + it * NTHREADS;              // 0..4095
        int tile = idx >> 10;                       // 0:Ah 1:Al 2:Bh 3:Bl
        int cidx = idx & 1023;
        int row = cidx >> 3, q = cidx & 7;
        int base = (tile & 2) ? j0 : i0;
        const uint4* src = (tile & 1) ? LO : HI;
        uint32_t off = (uint32_t)(row * 128) + (uint32_t)((q ^ (row & 7)) << 4);
        cp16(dbuf + tile * TILE_B + off, &src[(base + row) * 8 + q]);
    }
    if (tid < 256) {                                // 0..127: i rows, 128..255: j cols
        int g = ((tid >> 7) ? j0 : i0) + (tid & 127);
        cp16(dbuf + 4 * TILE_B + tid * 16, &g_meta[g]);
    }
}

// ---- one pair: GEMM (term-major) + dual-side epilogue (R14-verified) ----
template <bool DIAG>
__device__ __forceinline__ void compute_pair(uint32_t dbuf, const char* dbufp,
                                             int ti, int tj, int i0, int j0,
                                             int lane, int wr, int wc) {
    int mr = wr * 32, nc = wc * 32;
    int t8 = lane >> 3, rs = lane & 7;

    float d[2][4][4];
#pragma unroll
    for (int mf = 0; mf < 2; mf++)
#pragma unroll
        for (int nb = 0; nb < 4; nb++)
#pragma unroll
            for (int k = 0; k < 4; k++) d[mf][nb][k] = 0.f;

#pragma unroll
    for (int ks = 0; ks < 4; ks++) {
        uint32_t ah[2][4], al[2][4], bh[2][4], bl[2][4];
#pragma unroll
        for (int mf = 0; mf < 2; mf++) {
            int rowA = mr + mf * 16 + (t8 & 1) * 8 + rs;
            int ch = ks * 2 + (t8 >> 1);
            uint32_t sw = (uint32_t)(rowA * 128) + (uint32_t)((ch ^ (rowA & 7)) << 4);
            ldsm4(ah[mf], dbuf + 0 * TILE_B + sw);
            ldsm4(al[mf], dbuf + 1 * TILE_B + sw);
        }
#pragma unroll
        for (int nbp = 0; nbp < 2; nbp++) {
            int rowB = nc + nbp * 16 + (t8 >> 1) * 8 + rs;
            int ch = ks * 2 + (t8 & 1);
            uint32_t sw = (uint32_t)(rowB * 128) + (uint32_t)((ch ^ (rowB & 7)) << 4);
            ldsm4(bh[nbp], dbuf + 2 * TILE_B + sw);
            ldsm4(bl[nbp], dbuf + 3 * TILE_B + sw);
        }
        // term-major issue: 8 distinct accumulators between any dd reuse
#pragma unroll
        for (int mf = 0; mf < 2; mf++)
#pragma unroll
            for (int nbp = 0; nbp < 2; nbp++)
#pragma unroll
                for (int nbi = 0; nbi < 2; nbi++)
                    mma_bf16(d[mf][nbp * 2 + nbi], ah[mf],
                             bh[nbp][2 * nbi], bh[nbp][2 * nbi + 1]);
#pragma unroll
        for (int mf = 0; mf < 2; mf++)
#pragma unroll
            for (int nbp = 0; nbp < 2; nbp++)
#pragma unroll
                for (int nbi = 0; nbi < 2; nbi++)
                    mma_bf16(d[mf][nbp * 2 + nbi], ah[mf],
                             bl[nbp][2 * nbi], bl[nbp][2 * nbi + 1]);
#pragma unroll
        for (int mf = 0; mf < 2; mf++)
#pragma unroll
            for (int nbp = 0; nbp < 2; nbp++)
#pragma unroll
                for (int nbi = 0; nbi < 2; nbi++)
                    mma_bf16(d[mf][nbp * 2 + nbi], al[mf],
                             bh[nbp][2 * nbi], bh[nbp][2 * nbi + 1]);
    }

    const float4* meta_i = (const float4*)(dbufp + 4 * TILE_B);
    const float4* meta_j = meta_i + 128;

    float sqr[4], rur[4];
    int labr[4], rloc4[4];
#pragma unroll
    for (int f = 0; f < 4; f++) {
        int rloc = mr + (f >> 1) * 16 + (f & 1) * 8 + (lane >> 2);
        rloc4[f] = rloc;
        float4 m = meta_i[rloc];
        sqr[f] = m.x; rur[f] = 2.0f * m.y; labr[f] = __float_as_int(m.z);
    }
    float rse[4], rpr[4];
#pragma unroll
    for (int f = 0; f < 4; f++) { rse[f] = 0.f; rpr[f] = 1.f; }

#pragma unroll
    for (int nb = 0; nb < 4; nb++) {
#pragma unroll
        for (int ki = 0; ki < 2; ki++) {
            int cloc = nc + nb * 8 + (lane & 3) * 2 + ki;
            float4 mj = meta_j[cloc];
            int lj = __float_as_int(mj.z);
            float cse = 0.f, cpr = 1.f;
#pragma unroll
            for (int f = 0; f < 4; f++) {
                float dot = d[f >> 1][nb][(f & 1) * 2 + ki];
                float sqd = fmaxf(fmaf(-2.0f, dot, sqr[f] + mj.x), 0.f);
                float z = fmaf(sqd * rur[f], mj.y, 1.0f);   // z >= 1
                float s = fast_sqrt(fmaf(z, z, -1.0f));
                float rv = fmaxf(z - s, 1e-6f);      // exp(-d), one MUFU
                bool pos;
                float rve;
                if (DIAG) {
                    bool offd = (rloc4[f] != cloc);
                    pos = offd && (labr[f] == lj);
                    rve = offd ? rv : 0.f;
                } else {
                    pos = (labr[f] == lj);
                    rve = rv;
                }
                float rvp = pos ? rv : 1.f;
                rse[f] += rve; rpr[f] *= rvp;
                cse += rve; cpr *= rvp;
            }
            // col-side inline reduce over lane>>2 (skip on diagonal pairs)
            if (!DIAG) {
                float csl = __log2f(cpr);
                cse += __shfl_xor_sync(0xffffffffu, cse, 4);
                csl += __shfl_xor_sync(0xffffffffu, csl, 4);
                cse += __shfl_xor_sync(0xffffffffu, cse, 8);
                csl += __shfl_xor_sync(0xffffffffu, csl, 8);
                cse += __shfl_xor_sync(0xffffffffu, cse, 16);
                csl += __shfl_xor_sync(0xffffffffu, csl, 16);
                if (lane < 4) {
                    int cstore = nc + nb * 8 + lane * 2 + ki;
                    int slot = (ti * NQ + wr) * N_PTS + (j0 + cstore);
                    g_pse[slot] = cse;
                    g_psl[slot] = csl * 0.69314718055994531f;
                }
            }
        }
    }

    // row-side: reduce over lane&3; products <=8 factors (>=~6e-21), no renorm
#pragma unroll
    for (int f = 0; f < 4; f++) {
        float se = rse[f];
        float sl = __log2f(rpr[f]);
        se += __shfl_xor_sync(0xffffffffu, se, 1);
        sl += __shfl_xor_sync(0xffffffffu, sl, 1);
        se += __shfl_xor_sync(0xffffffffu, se, 2);
        sl += __shfl_xor_sync(0xffffffffu, sl, 2);
        if ((lane & 3) == 0) {
            int slot = (tj * NQ + wc) * N_PTS + (i0 + rloc4[f]);
            g_pse[slot] = se;
            g_psl[slot] = sl * 0.69314718055994531f;
        }
    }
}

// ---- main: persistent double-buffered HMMA pipeline (R9 structure) ----
__global__ __launch_bounds__(NTHREADS, 1)
void main_kernel() {
    extern __shared__ __align__(16) char dsm_raw[];
    uint32_t dsm0 = smem_u32(dsm_raw);
    uint32_t dsm = (dsm0 + 127u) & ~127u;
    char* dsmp = dsm_raw + (dsm - dsm0);

    int tid = threadIdx.x;
    int w = tid >> 5, lane = tid & 31;
    int wr = w & 3, wc = w >> 2;

    int p = blockIdx.x;
    int ti = 0, tj = 0;
    if (p < NPAIR) {
        decode_pair(p, ti, tj);
        prefetch_pair(dsm, ti * BM, tj * BM, tid);
    }
    CP_COMMIT();

    int it = 0;
    for (; p < NPAIR; p += GRID, it++) {
        uint32_t dbuf = dsm + (uint32_t)(it & 1) * BUF_B;
        const char* dbufp = dsmp + (it & 1) * BUF_B;

        int tin = 0, tjn = 0;
        int pn = p + GRID;
        if (pn < NPAIR) {
            decode_pair(pn, tin, tjn);
            prefetch_pair(dsm + (uint32_t)((it + 1) & 1) * BUF_B,
                          tin * BM, tjn * BM, tid);
        }
        CP_COMMIT();
        CP_WAIT1();
        __syncthreads();

        if (ti == tj)
            compute_pair<true>(dbuf, dbufp, ti, tj, ti * BM, tj * BM, lane, wr, wc);
        else
            compute_pair<false>(dbuf, dbufp, ti, tj, ti * BM, tj * BM, lane, wr, wc);
        __syncthreads();

        ti = tin; tj = tjn;
    }
}

// ---- rowred: label histogram + per-row loss + per-block partial sum ----
__global__ void rowred_kernel() {
    __shared__ int hist[NCLS];
    __shared__ float red[256];
    int t = threadIdx.x;
    if (t < NCLS) hist[t] = 0;
    __syncthreads();
    for (int k = t; k < N_PTS; k += 256)
        atomicAdd(&hist[__float_as_int(g_meta[k].z) & (NCLS - 1)], 1);
    __syncthreads();

    int i = blockIdx.x * blockDim.x + t;
    float se = 0.f, sl = 0.f;
#pragma unroll 8
    for (int q = 0; q < NQ * NT; q++) {
        se += g_pse[q * N_PTS + i];
        sl += g_psl[q * N_PTS + i];
    }
    int lab = __float_as_int(g_meta[i].z) & (NCLS - 1);
    int P = hist[lab] - 1;
    float logA = __logf(fmaxf(se, 1e-30f));
    red[t] = logA - sl / (float)(P > 0 ? P : 1);
    __syncthreads();
    for (int s = 128; s > 0; s >>= 1) {
        if (t < s) red[t] += red[t + s];
        __syncthreads();
    }
    if (t == 0) g_blocksum[blockIdx.x] = red[0];
}

__global__ void final_kernel(float* __restrict__ out) {
    int t = threadIdx.x;
    float v = g_blocksum[t];
#pragma unroll
    for (int s = 16; s > 0; s >>= 1)
        v += __shfl_xor_sync(0xffffffffu, v, s);
    if (t == 0) out[0] = v;
}

extern "C" void kernel_launch(void* const* d_in, const int* in_sizes, int n_in,
                              void* d_out, int out_size) {
    const float* pts = (const float*)d_in[0];
    const long long* labs = (const long long*)d_in[1];
    cudaFuncSetAttribute(main_kernel, cudaFuncAttributeMaxDynamicSharedMemorySize,
                         2 * BUF_B + 128);
    prep_kernel<<<N_PTS / 256, 256>>>(pts, labs);
    main_kernel<<<GRID, NTHREADS, 2 * BUF_B + 128>>>();
    rowred_kernel<<<N_PTS / 256, 256>>>();
    final_kernel<<<1, 32>>>((float*)d_out);
}